// round 10
// baseline (speedup 1.0000x reference)
#include <cuda_runtime.h>
#include <cuda_bf16.h>
#include <cstdint>
#include <math.h>

// ---------------------------------------------------------------------------
#define PIX33 1089
#define PIXPAD 1152
#define PIX65 4225
#define PIX129 16641
#define CIN 128
#define COUT 768
#define NB 8
#define NCH 19
#define NCHUNK 12          // 768 / 64 o-rows per chunk

typedef unsigned long long u64;

__device__ __forceinline__ u64 pack2(float lo, float hi) {
    u64 r; asm("mov.b64 %0, {%1, %2};" : "=l"(r) : "f"(lo), "f"(hi)); return r;
}
__device__ __forceinline__ void unpack2(float& lo, float& hi, u64 v) {
    asm("mov.b64 {%0, %1}, %2;" : "=f"(lo), "=f"(hi) : "l"(v));
}
__device__ __forceinline__ void fma2(u64& d, u64 a, u64 b) {
    asm("fma.rn.f32x2 %0, %1, %2, %3;" : "=l"(d) : "l"(a), "l"(b), "l"(d));
}
__device__ __forceinline__ void mma16816(float* c, uint32_t a0, uint32_t a1,
                                         uint32_t a2, uint32_t a3,
                                         uint32_t b0, uint32_t b1) {
    asm volatile(
        "mma.sync.aligned.m16n8k16.row.col.f32.bf16.bf16.f32 "
        "{%0,%1,%2,%3}, {%4,%5,%6,%7}, {%8,%9}, {%0,%1,%2,%3};"
        : "+f"(c[0]), "+f"(c[1]), "+f"(c[2]), "+f"(c[3])
        : "r"(a0), "r"(a1), "r"(a2), "r"(a3), "r"(b0), "r"(b1));
}
__device__ __forceinline__ void ldsm4(uint32_t& r0, uint32_t& r1,
                                      uint32_t& r2, uint32_t& r3, uint32_t addr) {
    asm volatile("ldmatrix.sync.aligned.m8n8.x4.shared.b16 {%0,%1,%2,%3}, [%4];"
                 : "=r"(r0), "=r"(r1), "=r"(r2), "=r"(r3) : "r"(addr));
}
__device__ __forceinline__ float2 bf2f(uint32_t u) {
    __nv_bfloat162 h = *(__nv_bfloat162*)&u;
    return __bfloat1622float2(h);
}
__device__ __forceinline__ uint32_t f2bf(float a, float b) {
    __nv_bfloat162 h = __floats2bfloat162_rn(a, b);
    return *(uint32_t*)&h;
}

__device__ __align__(16) __nv_bfloat16 g_Wbf[COUT * CIN];        // [o][k]
__device__ __align__(16) __nv_bfloat16 g_Sbf[NB * PIXPAD * CIN]; // [b][pix33][k]
__device__ __align__(16) float g_Ut[NB * NCH * PIX129];
__device__ __align__(16) float g_Us[NB * NCH * PIX129];
__device__ double g_pi;
__device__ double g_d[2][NB * NCH];
__device__ double g_Wz[2][NB * NCH];
__device__ double g_R[2][NB][190];

static cudaStream_t g_s2;
static cudaEvent_t g_e1, g_e2;
namespace {
struct StreamInit {
    StreamInit() {
        cudaStreamCreateWithFlags(&g_s2, cudaStreamNonBlocking);
        cudaEventCreateWithFlags(&g_e1, cudaEventDisableTiming);
        cudaEventCreateWithFlags(&g_e2, cudaEventDisableTiming);
    }
};
static StreamInit g_si;
}

// ---------------------------------------------------------------------------
__global__ void zero_kernel() {
    int t = blockIdx.x * blockDim.x + threadIdx.x;
    if (t == 0) g_pi = 0.0;
    if (t < NB * NCH) {
        g_d[0][t] = 0.0; g_d[1][t] = 0.0;
        g_Wz[0][t] = 0.0; g_Wz[1][t] = 0.0;
    }
    if (t < 2 * NB * 190) ((double*)g_R)[t] = 0.0;
}

__global__ void wbf_kernel(const float* __restrict__ conv_w) {
    int idx = blockIdx.x * blockDim.x + threadIdx.x;
    if (idx < COUT * CIN)
        g_Wbf[idx] = __float2bfloat16(conv_w[idx]);
}

// s_out fp32 [b][c][pix] -> bf16 transposed [b][pix][c], 32 channels per block.
__global__ __launch_bounds__(256) void sbf_kernel(const float* __restrict__ s_out) {
    __shared__ float t[64][33];
    int b = blockIdx.y, p0 = blockIdx.x * 64, cg = blockIdx.z * 32;
    int tid = threadIdx.x;
    int px = tid & 63, c4 = tid >> 6;
    const float* base = s_out + (size_t)b * CIN * PIX33;
#pragma unroll
    for (int c0 = 0; c0 < 32; c0 += 4) {
        int c = c0 + c4;
        int pix = p0 + px;
        t[px][c] = (pix < PIX33) ? base[(size_t)(cg + c) * PIX33 + pix] : 0.f;
    }
    __syncthreads();
#pragma unroll
    for (int i = 0; i < 4; i++) {
        int id = tid + i * 256;
        int r = id >> 4, cp = id & 15;
        *(uint32_t*)&g_Sbf[((size_t)b * PIXPAD + p0 + r) * CIN + cg + cp * 2] =
            f2bf(t[r][cp * 2], t[r][cp * 2 + 1]);
    }
}

// ---------------------------------------------------------------------------
// FUSED: per block = 64 pixels of the 65x65 grid, batch b.
//  1. build s65 bf16 tile [64 pix][128 k] in SMEM via half-grid interp of g_Sbf
//  2. for 12 o-chunks of 64: MMA (64o x 64pix x 128k), epilogue streams t_out,
//     accumulates per-pixel S1=sum e^zt, S2=sum zt e^zt, S3=sum zs e^zt,
//     Ss=sum e^zs in registers.
//  3. butterfly + SMEM reduce -> per-pixel KL -> one double atomic.
// ---------------------------------------------------------------------------
__global__ __launch_bounds__(256) void fused_pi_kernel(const float* __restrict__ t_out,
                                                       const float* __restrict__ bias) {
    int b  = blockIdx.y;
    int p0 = blockIdx.x * 64;

    __shared__ __align__(16) __nv_bfloat16 Asm[64][136];
    __shared__ __align__(16) __nv_bfloat16 Bsm[64][136];
    __shared__ float biasS[64];
    __shared__ float Sred[4][4][64];
    __shared__ float redv[64];

    int tid = threadIdx.x;
    int w = tid >> 5, lane = tid & 31;

    // --- Step 1: build s65 tile rows w*8 .. w*8+7 ---
    {
        const __nv_bfloat16* base = g_Sbf + (size_t)b * PIXPAD * CIN;
#pragma unroll
        for (int rr = 0; rr < 8; rr++) {
            int r = w * 8 + rr;
            int p = p0 + r;
            if (p < PIX65) {
                int y = p / 65, x = p - y * 65;
                int y0 = y >> 1, x0 = x >> 1;
                int y1 = min(y0 + 1, 32), x1 = min(x0 + 1, 32);
                float wy = (y & 1) * 0.5f, wx = (x & 1) * 0.5f;
                float w00 = (1.f - wy) * (1.f - wx), w01 = (1.f - wy) * wx;
                float w10 = wy * (1.f - wx),         w11 = wy * wx;
                const uint2* q00 = (const uint2*)(base + (size_t)(y0 * 33 + x0) * CIN);
                const uint2* q01 = (const uint2*)(base + (size_t)(y0 * 33 + x1) * CIN);
                const uint2* q10 = (const uint2*)(base + (size_t)(y1 * 33 + x0) * CIN);
                const uint2* q11 = (const uint2*)(base + (size_t)(y1 * 33 + x1) * CIN);
                uint2 v00 = q00[lane], v01 = q01[lane];
                uint2 v10 = q10[lane], v11 = q11[lane];
                float2 a0 = bf2f(v00.x), a1 = bf2f(v00.y);
                float2 b0 = bf2f(v01.x), b1 = bf2f(v01.y);
                float2 c0 = bf2f(v10.x), c1 = bf2f(v10.y);
                float2 d0 = bf2f(v11.x), d1 = bf2f(v11.y);
                float f0 = w00 * a0.x + w01 * b0.x + w10 * c0.x + w11 * d0.x;
                float f1 = w00 * a0.y + w01 * b0.y + w10 * c0.y + w11 * d0.y;
                float f2 = w00 * a1.x + w01 * b1.x + w10 * c1.x + w11 * d1.x;
                float f3 = w00 * a1.y + w01 * b1.y + w10 * c1.y + w11 * d1.y;
                uint2 outv;
                outv.x = f2bf(f0, f1);
                outv.y = f2bf(f2, f3);
                *(uint2*)&Bsm[r][lane * 4] = outv;
            } else {
                uint2 z; z.x = 0; z.y = 0;
                *(uint2*)&Bsm[r][lane * 4] = z;
            }
        }
    }

    // --- frag addressing (identical mapping to validated R8 kernel) ---
    int mq = w & 3, nh = w >> 2;
    int lr = lane >> 2;
    int lc = (lane & 3) * 2;
    uint32_t sA = (uint32_t)__cvta_generic_to_shared(&Asm[0][0]);
    uint32_t sB = (uint32_t)__cvta_generic_to_shared(&Bsm[0][0]);
    uint32_t aAddr = sA + (uint32_t)((mq * 16 + (lane & 15)) * 136 + ((lane >> 4) << 3)) * 2;
    int quad = lane >> 3, r8 = lane & 7;
    uint32_t bAddr0 = sB + (uint32_t)((nh * 32 + ((quad >> 1) << 3) + r8) * 136
                                      + ((quad & 1) << 3)) * 2;
    uint32_t bAddr1 = bAddr0 + (uint32_t)(16 * 136) * 2;

    float S1l[8], S2l[8], S3l[8], Ssl[8];
#pragma unroll
    for (int s = 0; s < 8; s++) { S1l[s] = 0.f; S2l[s] = 0.f; S3l[s] = 0.f; Ssl[s] = 0.f; }

    const float* tbase = t_out + (size_t)b * COUT * PIX65;

    for (int oc = 0; oc < NCHUNK; oc++) {
        __syncthreads();   // B-tile ready (oc=0) / previous chunk's MMA done
        // load W chunk [64 o][128 k]
        const uint4* src = (const uint4*)(g_Wbf + (size_t)(oc * 64) * CIN);
#pragma unroll
        for (int i = 0; i < 4; i++) {
            int id = tid + i * 256;
            int r = id >> 4, c = id & 15;
            *(uint4*)&Asm[r][c * 8] = src[r * 16 + c];
        }
        if (tid < 64) biasS[tid] = bias[oc * 64 + tid];
        __syncthreads();

        float acc[4][4];
#pragma unroll
        for (int t = 0; t < 4; t++)
#pragma unroll
            for (int j = 0; j < 4; j++) acc[t][j] = 0.f;

#pragma unroll
        for (int ks = 0; ks < 8; ks++) {
            uint32_t ko = (uint32_t)(ks * 16) * 2;
            uint32_t a0, a1, a2, a3;
            ldsm4(a0, a1, a2, a3, aAddr + ko);
            uint32_t b00, b01, b10, b11;
            ldsm4(b00, b01, b10, b11, bAddr0 + ko);
            mma16816(acc[0], a0, a1, a2, a3, b00, b01);
            mma16816(acc[1], a0, a1, a2, a3, b10, b11);
            uint32_t c00, c01, c10, c11;
            ldsm4(c00, c01, c10, c11, bAddr1 + ko);
            mma16816(acc[2], a0, a1, a2, a3, c00, c01);
            mma16816(acc[3], a0, a1, a2, a3, c10, c11);
        }

        // epilogue: stream zt, accumulate stats
        int oA = mq * 16 + lr;
        int oB = oA + 8;
        float bbA = biasS[oA], bbB = biasS[oB];
        const float* rowA = tbase + (size_t)(oc * 64 + oA) * PIX65;
        const float* rowB = tbase + (size_t)(oc * 64 + oB) * PIX65;
#pragma unroll
        for (int nt = 0; nt < 4; nt++) {
            int px0 = p0 + nh * 32 + nt * 8 + lc;
            int q0 = min(px0, PIX65 - 1);
            int q1 = min(px0 + 1, PIX65 - 1);
            float zt00 = rowA[q0], zt01 = rowA[q1];
            float zt10 = rowB[q0], zt11 = rowB[q1];
            float zs00 = acc[nt][0] + bbA, zs01 = acc[nt][1] + bbA;
            float zs10 = acc[nt][2] + bbB, zs11 = acc[nt][3] + bbB;
            int s0 = nt * 2, s1 = s0 + 1;
            float e;
            e = __expf(zt00); S1l[s0] += e; S2l[s0] += zt00 * e; S3l[s0] += zs00 * e;
            Ssl[s0] += __expf(zs00);
            e = __expf(zt01); S1l[s1] += e; S2l[s1] += zt01 * e; S3l[s1] += zs01 * e;
            Ssl[s1] += __expf(zs01);
            e = __expf(zt10); S1l[s0] += e; S2l[s0] += zt10 * e; S3l[s0] += zs10 * e;
            Ssl[s0] += __expf(zs10);
            e = __expf(zt11); S1l[s1] += e; S2l[s1] += zt11 * e; S3l[s1] += zs11 * e;
            Ssl[s1] += __expf(zs11);
        }
    }

    // butterfly over lr (lanes stride 4, 8, 16)
#pragma unroll
    for (int s = 0; s < 8; s++) {
#pragma unroll
        for (int o = 4; o <= 16; o <<= 1) {
            S1l[s] += __shfl_xor_sync(0xFFFFFFFFu, S1l[s], o);
            S2l[s] += __shfl_xor_sync(0xFFFFFFFFu, S2l[s], o);
            S3l[s] += __shfl_xor_sync(0xFFFFFFFFu, S3l[s], o);
            Ssl[s] += __shfl_xor_sync(0xFFFFFFFFu, Ssl[s], o);
        }
    }
    if (lr == 0) {
#pragma unroll
        for (int s = 0; s < 8; s++) {
            int px = nh * 32 + (s >> 1) * 8 + lc + (s & 1);
            Sred[0][mq][px] = S1l[s];
            Sred[1][mq][px] = S2l[s];
            Sred[2][mq][px] = S3l[s];
            Ssl[s] = Ssl[s];  // keep
            Sred[3][mq][px] = Ssl[s];
        }
    }
    __syncthreads();

    if (tid < 64) {
        int p = p0 + tid;
        float v = 0.f;
        if (p < PIX65) {
            float S1 = Sred[0][0][tid] + Sred[0][1][tid] + Sred[0][2][tid] + Sred[0][3][tid];
            float S2 = Sred[1][0][tid] + Sred[1][1][tid] + Sred[1][2][tid] + Sred[1][3][tid];
            float S3 = Sred[2][0][tid] + Sred[2][1][tid] + Sred[2][2][tid] + Sred[2][3][tid];
            float Ss = Sred[3][0][tid] + Sred[3][1][tid] + Sred[3][2][tid] + Sred[3][3][tid];
            float inv = 1.f / S1;
            v = S2 * inv - logf(S1) - S3 * inv + logf(Ss);
        }
        redv[tid] = v;
    }
    __syncthreads();
    if (tid == 0) {
        double s = 0.0;
        for (int i = 0; i < 64; i++) s += (double)redv[i];
        atomicAdd(&g_pi, s);
    }
}

// ---------------------------------------------------------------------------
__device__ __forceinline__ void prep_reduce_store(float dloc, float wloc,
                                                  int side, int row) {
    __shared__ float rd[256], rw[256];
    int tid = threadIdx.x;
    rd[tid] = dloc; rw[tid] = wloc;
    __syncthreads();
    for (int o = 128; o; o >>= 1) {
        if (tid < o) { rd[tid] += rd[tid + o]; rw[tid] += rw[tid + o]; }
        __syncthreads();
    }
    if (tid == 0) {
        atomicAdd(&g_d[side][row], (double)rd[0]);
        atomicAdd(&g_Wz[side][row], (double)rw[0]);
    }
}

__global__ void prep_kernel(const float* __restrict__ t_logit,
                            const float* __restrict__ s_logit) {
    int side = blockIdx.z;            // 0=s, 1=t
    int row = blockIdx.y;
    int k = blockIdx.x * 256 + threadIdx.x;
    float dloc = 0.f, wloc = 0.f;
    if (k < PIX129) {
        float z;
        if (side == 0) {
            z = s_logit[(size_t)row * PIX129 + k];
        } else {
            int y = k / 129, x = k - y * 129;
            int y0 = y >> 1, x0 = x >> 1;
            int y1 = min(y0 + 1, 64), x1 = min(x0 + 1, 64);
            float wy = (y & 1) * 0.5f, wx = (x & 1) * 0.5f;
            const float* src = t_logit + (size_t)row * PIX65;
            float top = (1.f - wx) * src[y0 * 65 + x0] + wx * src[y0 * 65 + x1];
            float bot = (1.f - wx) * src[y1 * 65 + x0] + wx * src[y1 * 65 + x1];
            z = (1.f - wy) * top + wy * bot;
        }
        float u = __expf(z);
        (side ? g_Ut : g_Us)[(size_t)row * PIX129 + k] = u;
        dloc = u; wloc = u * z;
    }
    prep_reduce_store(dloc, wloc, side, row);
}

// ---------------------------------------------------------------------------
__global__ void gram_kernel() {
    int side = blockIdx.z;            // 0=s, 1=t
    int b    = blockIdx.y;
    int k0   = blockIdx.x * 512;
    const float* U = (side ? g_Ut : g_Us) + (size_t)b * NCH * PIX129;

    __shared__ __align__(8) float sm[NCH][514];
    int tid = threadIdx.x;
    for (int idx = tid; idx < NCH * 512; idx += 256) {
        int i = idx >> 9, kk = idx & 511;
        int k = k0 + kk;
        sm[i][kk] = (k < PIX129) ? U[(size_t)i * PIX129 + k] : 0.f;
    }
    __syncthreads();

    if (tid < 190) {
        int i = 0, t = tid;
        while (t >= NCH - i) { t -= NCH - i; i++; }
        int j = i + t;
        const u64* ri = (const u64*)&sm[i][0];
        const u64* rj = (const u64*)&sm[j][0];
        u64 acc2 = pack2(0.f, 0.f);
#pragma unroll 4
        for (int kk = 0; kk < 256; kk++) fma2(acc2, ri[kk], rj[kk]);
        float lo, hi;
        unpack2(lo, hi, acc2);
        atomicAdd(&g_R[side][b][tid], (double)(lo + hi));
    }
}

// ---------------------------------------------------------------------------
__global__ void finalize_kernel(float* __restrict__ out) {
    int tid = threadIdx.x;
    __shared__ double sE[2][NCH];
    __shared__ double sG[2][361];
    __shared__ double sS[2][361];
    __shared__ double sN[2][NCH];
    __shared__ double red[512];

    if (tid < 2 * NCH) {
        int side = tid / NCH, i = tid % NCH;
        double e = 0.0;
        for (int b = 0; b < NB; b++) {
            double d = g_d[side][b * NCH + i];
            e += g_Wz[side][b * NCH + i] / d - log(d);
        }
        sE[side][i] = e;
    }
    if (tid < 361) {
        int i = tid / NCH, j = tid % NCH;
        int mi = min(i, j), mj = max(i, j);
        int p = mi * NCH - mi * (mi - 1) / 2 + (mj - mi);
        for (int side = 0; side < 2; side++) {
            double g = 0.0;
            for (int b = 0; b < NB; b++)
                g += g_R[side][b][p] /
                     (g_d[side][b * NCH + i] * g_d[side][b * NCH + j]);
            sG[side][tid] = g;
        }
    }
    __syncthreads();
    if (tid < 361) {
        int i = tid / NCH, j = tid % NCH;
        int mx = max(i, j);
        sS[0][tid] = (sE[0][mx] - sG[0][tid]) / (double)NB;
        sS[1][tid] = (sE[1][mx] - sG[1][tid]) / (double)NB;
    }
    __syncthreads();
    if (tid < 2 * NCH) {
        int side = tid / NCH, i = tid % NCH;
        double s = 0.0;
        for (int j = 0; j < NCH; j++) {
            double v = sS[side][i * NCH + j];
            s += v * v;
        }
        double n = sqrt(s);
        sN[side][i] = (n > 1e-12) ? n : 1e-12;
    }
    __syncthreads();
    double v = 0.0;
    if (tid < 361) {
        int i = tid / NCH;
        double dd = sS[0][tid] / sN[0][i] - sS[1][tid] / sN[1][i];
        v = dd * dd;
    }
    red[tid] = v;
    __syncthreads();
    for (int o = 256; o; o >>= 1) {
        if (tid < o) red[tid] += red[tid + o];
        __syncthreads();
    }
    if (tid == 0) {
        out[0] = (float)(g_pi / 25958400.0);
        out[1] = (float)red[0];
    }
}

// ---------------------------------------------------------------------------
extern "C" void kernel_launch(void* const* d_in, const int* in_sizes, int n_in,
                              void* d_out, int out_size) {
    const float *ptr[6] = {nullptr, nullptr, nullptr, nullptr, nullptr, nullptr};
    const int want[6] = {1115136, 25958400, 642200, 2529912, 98304, 768};

    for (int i = 0; i < n_in; i++) {
        long long s = in_sizes[i];
        for (int k = 0; k < 6; k++) {
            if (s == (long long)want[k] || s == 4LL * want[k]) {
                if (!ptr[k]) ptr[k] = (const float*)d_in[i];
            }
        }
    }
    if (n_in >= 6) {
        for (int k = 0; k < 6; k++)
            if (!ptr[k]) ptr[k] = (const float*)d_in[k];
    }

    const float* s_out   = ptr[0];
    const float* t_out   = ptr[1];
    const float* t_logit = ptr[2];
    const float* s_logit = ptr[3];
    const float* conv_w  = ptr[4];
    const float* conv_b  = ptr[5];

    zero_kernel<<<15, 256>>>();
    cudaEventRecord(g_e1, 0);
    cudaStreamWaitEvent(g_s2, g_e1, 0);

    // Chain 1 (default stream): bf16 prep + fused gemm/resize/softmax/KL.
    wbf_kernel<<<(COUT * CIN + 255) / 256, 256>>>(conv_w);
    sbf_kernel<<<dim3(18, NB, 4), 256>>>(s_out);
    fused_pi_kernel<<<dim3(67, NB), 256>>>(t_out, conv_b);

    // Chain 2 (side stream): lo path.
    prep_kernel<<<dim3((PIX129 + 255) / 256, NB * NCH, 2), 256, 0, g_s2>>>(t_logit, s_logit);
    gram_kernel<<<dim3((PIX129 + 511) / 512, NB, 2), 256, 0, g_s2>>>();

    cudaEventRecord(g_e2, g_s2);
    cudaStreamWaitEvent(0, g_e2, 0);
    finalize_kernel<<<1, 512>>>((float*)d_out);
}